// round 5
// baseline (speedup 1.0000x reference)
#include <cuda_runtime.h>
#include <cuda_bf16.h>
#include <cstdint>

// ---------------------------------------------------------------------------
// GNN_30064771072959: 2-layer GraphConv (norm='both'), N=100000, E=1.6M, F=D=128
//   norms: deg^-0.5 (clamped >=1) from src/dst histograms
//   layer: x = (h .* ns) @ W ; agg = scatter_add(x[src] -> dst) ; out = agg .* nd + b [; relu]
// Layer-1 epilogue (agg .* nd + b1, relu) is FUSED into the layer-2 GEMM A-load.
// All scratch lives in __device__ globals. kernel_launch = launches only.
// ---------------------------------------------------------------------------

#define FDIM 128
#define NMAX 131072

__device__ float g_x  [(size_t)NMAX * FDIM];   // layer-1 projected features
__device__ float g_agg[(size_t)NMAX * FDIM];   // scatter-add target
__device__ float g_degout[NMAX];
__device__ float g_degin [NMAX];
__device__ float g_ns[NMAX];                   // norm_src
__device__ float g_nd[NMAX];                   // norm_dst

// ---------------- zeroing ----------------
__global__ void zero_deg_kernel(int N) {
    int t = blockIdx.x * blockDim.x + threadIdx.x;
    if (t < N) { g_degout[t] = 0.f; g_degin[t] = 0.f; }
}

__global__ void zero_agg_kernel(int n4) {   // n4 = N * 32 float4s
    int t = blockIdx.x * blockDim.x + threadIdx.x;
    if (t < n4) reinterpret_cast<float4*>(g_agg)[t] = make_float4(0.f, 0.f, 0.f, 0.f);
}

// ---------------- degrees / norms ----------------
__global__ void degree_kernel(const int* __restrict__ src, const int* __restrict__ dst, int E) {
    int e = blockIdx.x * blockDim.x + threadIdx.x;
    if (e >= E) return;
    atomicAdd(&g_degout[src[e]], 1.f);
    atomicAdd(&g_degin [dst[e]], 1.f);
}

__global__ void norm_kernel(int N) {
    int t = blockIdx.x * blockDim.x + threadIdx.x;
    if (t >= N) return;
    g_ns[t] = rsqrtf(fmaxf(g_degout[t], 1.f));
    g_nd[t] = rsqrtf(fmaxf(g_degin [t], 1.f));
}

// ---------------- GEMM: C[N,128] = (f(A) .* ns) @ W[128,128] ----------------
// a_mode 0: A row = A_ext[row] (plain)
// a_mode 1: A row = relu(g_agg[row] .* nd[row] + bprev)  (fused layer-1 epilogue)
// c_sel:    0 -> C = C_ext, 1 -> C = g_x.
#define BM 64
#define BK 32

__global__ void __launch_bounds__(256) gemm_rowscale_kernel(
    const float* __restrict__ A_ext, const float* __restrict__ W,
    const float* __restrict__ bprev, float* __restrict__ C_ext,
    int N, int a_mode, int c_sel)
{
    float* C = c_sel ? (float*)g_x : C_ext;

    __shared__ float As[BM][BK + 1];
    __shared__ float Ws[BK][FDIM];

    const int m0  = blockIdx.x * BM;
    const int tid = threadIdx.x;
    const int tx  = tid & 15;   // col group: cols tx*8 .. tx*8+7
    const int ty  = tid >> 4;   // row group: rows ty*4 .. ty*4+3

    float acc[4][8];
    #pragma unroll
    for (int i = 0; i < 4; i++)
        #pragma unroll
        for (int j = 0; j < 8; j++) acc[i][j] = 0.f;

    for (int k0 = 0; k0 < FDIM; k0 += BK) {
        // load A tile (64x32), fusing row-scale (and optionally the previous
        // layer's epilogue): 512 float4, 2/thread
        #pragma unroll
        for (int i = 0; i < 2; i++) {
            int lin = tid + i * 256;         // float4 index
            int r   = lin >> 3;              // row in tile
            int c   = (lin & 7) << 2;        // col in tile
            int row = m0 + r;
            float4 v = make_float4(0.f, 0.f, 0.f, 0.f);
            if (row < N) {
                float s = g_ns[row];
                if (a_mode == 0) {
                    v = *reinterpret_cast<const float4*>(A_ext + (size_t)row * FDIM + k0 + c);
                } else {
                    float4 a  = *reinterpret_cast<const float4*>(g_agg + (size_t)row * FDIM + k0 + c);
                    float4 bb = *reinterpret_cast<const float4*>(bprev + k0 + c);
                    float  nd = g_nd[row];
                    v.x = fmaxf(fmaf(a.x, nd, bb.x), 0.f);
                    v.y = fmaxf(fmaf(a.y, nd, bb.y), 0.f);
                    v.z = fmaxf(fmaf(a.z, nd, bb.z), 0.f);
                    v.w = fmaxf(fmaf(a.w, nd, bb.w), 0.f);
                }
                v.x *= s; v.y *= s; v.z *= s; v.w *= s;
            }
            As[r][c + 0] = v.x; As[r][c + 1] = v.y;
            As[r][c + 2] = v.z; As[r][c + 3] = v.w;
        }
        // load W tile (32x128): 1024 float4, 4/thread
        #pragma unroll
        for (int i = 0; i < 4; i++) {
            int lin = tid + i * 256;
            int r   = lin >> 5;
            int c   = (lin & 31) << 2;
            *reinterpret_cast<float4*>(&Ws[r][c]) =
                *reinterpret_cast<const float4*>(W + (size_t)(k0 + r) * FDIM + c);
        }
        __syncthreads();

        #pragma unroll
        for (int kk = 0; kk < BK; kk++) {
            float a[4];
            #pragma unroll
            for (int i = 0; i < 4; i++) a[i] = As[ty * 4 + i][kk];
            float4 w0 = *reinterpret_cast<const float4*>(&Ws[kk][tx * 8]);
            float4 w1 = *reinterpret_cast<const float4*>(&Ws[kk][tx * 8 + 4]);
            #pragma unroll
            for (int i = 0; i < 4; i++) {
                acc[i][0] = fmaf(a[i], w0.x, acc[i][0]);
                acc[i][1] = fmaf(a[i], w0.y, acc[i][1]);
                acc[i][2] = fmaf(a[i], w0.z, acc[i][2]);
                acc[i][3] = fmaf(a[i], w0.w, acc[i][3]);
                acc[i][4] = fmaf(a[i], w1.x, acc[i][4]);
                acc[i][5] = fmaf(a[i], w1.y, acc[i][5]);
                acc[i][6] = fmaf(a[i], w1.z, acc[i][6]);
                acc[i][7] = fmaf(a[i], w1.w, acc[i][7]);
            }
        }
        __syncthreads();
    }

    // store 4 rows x 8 cols
    #pragma unroll
    for (int i = 0; i < 4; i++) {
        int row = m0 + ty * 4 + i;
        if (row >= N) continue;
        float* cp = C + (size_t)row * FDIM + tx * 8;
        *reinterpret_cast<float4*>(cp)     = make_float4(acc[i][0], acc[i][1], acc[i][2], acc[i][3]);
        *reinterpret_cast<float4*>(cp + 4) = make_float4(acc[i][4], acc[i][5], acc[i][6], acc[i][7]);
    }
}

// ---------------- SpMM: agg[dst] += x[src], one warp per edge ----------------
// x_sel: 0 -> X = X_ext, 1 -> X = g_x.
__global__ void __launch_bounds__(256) spmm_kernel(
    const float* __restrict__ X_ext, const int* __restrict__ src,
    const int* __restrict__ dst, int E, int x_sel)
{
    const float* X = x_sel ? (const float*)g_x : X_ext;
    int t = blockIdx.x * blockDim.x + threadIdx.x;
    int e = t >> 5;
    if (e >= E) return;
    int j = t & 31;
    int s = __ldg(src + e);
    int d = __ldg(dst + e);
    const float4* sp = reinterpret_cast<const float4*>(X + (size_t)s * FDIM) + j;
    float*        p  = g_agg + (size_t)d * FDIM + j * 4;
    float4 v = *sp;
    asm volatile("red.global.add.v4.f32 [%0], {%1,%2,%3,%4};"
                 :: "l"(p), "f"(v.x), "f"(v.y), "f"(v.z), "f"(v.w)
                 : "memory");
}

// ---------------- final epilogue: out = agg .* nd + b ----------------
__global__ void epilogue_kernel(const float* __restrict__ b, float* __restrict__ OUT, int N)
{
    int t = blockIdx.x * blockDim.x + threadIdx.x;
    int row = t >> 5;
    if (row >= N) return;
    int j = t & 31;
    float4 v  = reinterpret_cast<const float4*>(g_agg + (size_t)row * FDIM)[j];
    float4 bb = reinterpret_cast<const float4*>(b)[j];
    float  s  = g_nd[row];
    v.x = fmaf(v.x, s, bb.x);
    v.y = fmaf(v.y, s, bb.y);
    v.z = fmaf(v.z, s, bb.z);
    v.w = fmaf(v.w, s, bb.w);
    reinterpret_cast<float4*>(OUT + (size_t)row * FDIM)[j] = v;
}

// ---------------------------------------------------------------------------
extern "C" void kernel_launch(void* const* d_in, const int* in_sizes, int n_in,
                              void* d_out, int out_size)
{
    const float* feature = (const float*)d_in[0];
    const int*   src     = (const int*)  d_in[1];
    const int*   dst     = (const int*)  d_in[2];
    const float* W1      = (const float*)d_in[3];
    const float* b1      = (const float*)d_in[4];
    const float* W2      = (const float*)d_in[5];
    const float* b2      = (const float*)d_in[6];
    float* out = (float*)d_out;

    const int N = in_sizes[0] / FDIM;
    const int E = in_sizes[1];

    const int TB = 256;
    const int grid_N    = (N + TB - 1) / TB;
    const int grid_E    = (E + TB - 1) / TB;
    const int grid_Nf4  = (N * 32 + TB - 1) / TB;                 // N*32 float4 threads
    const int grid_edge = (int)(((long long)E * 32 + TB - 1) / TB);
    const int grid_gemm = (N + BM - 1) / BM;

    // degrees + norms
    zero_deg_kernel<<<grid_N, TB>>>(N);
    degree_kernel  <<<grid_E, TB>>>(src, dst, E);
    norm_kernel    <<<grid_N, TB>>>(N);

    // ---- layer 1 : x1 = (feature .* ns) @ W1 -> g_x ; agg1 -> g_agg ----
    gemm_rowscale_kernel<<<grid_gemm, TB>>>(feature, W1, nullptr, nullptr, N,
                                            /*a_mode=*/0, /*c_sel=*/1);
    zero_agg_kernel<<<grid_Nf4, TB>>>(N * 32);
    spmm_kernel<<<grid_edge, TB>>>(nullptr, src, dst, E, /*x_sel=*/1);

    // ---- layer 2 : x2 = (relu(agg1 .* nd + b1) .* ns) @ W2 -> d_out ----
    gemm_rowscale_kernel<<<grid_gemm, TB>>>(nullptr, W2, b1, out, N,
                                            /*a_mode=*/1, /*c_sel=*/0);
    zero_agg_kernel<<<grid_Nf4, TB>>>(N * 32);
    spmm_kernel<<<grid_edge, TB>>>(out, src, dst, E, /*x_sel=*/0);
    epilogue_kernel<<<grid_Nf4, TB>>>(b2, out, N);    // final -> d_out
}

// round 15
// speedup vs baseline: 1.3392x; 1.3392x over previous
#include <cuda_runtime.h>
#include <cuda_bf16.h>
#include <cstdint>

// ---------------------------------------------------------------------------
// GNN_30064771072959: 2-layer GraphConv, N=100000, E=1.6M, F=D=128
// R6 design:
//   - dst-CSR built per call (histogram -> 1-block scan -> atomic fill)
//   - SpMM = warp-per-dst-row register-accumulating gather, epilogue fused
//   - GEMM = 128x128x16 tiles, 8x8 microtile, transposed As
// ---------------------------------------------------------------------------

#define FDIM   128
#define NMAX   131072
#define EMAX   2097152
#define SCAN_T 1024

__device__ float g_x [(size_t)NMAX * FDIM];    // x1 / x2 (projected feats)
__device__ float g_h [(size_t)NMAX * FDIM];    // h1 (post-aggregation layer 1)
__device__ int   g_csrsrc[EMAX];
__device__ int   g_rowptr[NMAX + 1];
__device__ int   g_cursor[NMAX];
__device__ int   g_din [NMAX];
__device__ int   g_dout[NMAX];
__device__ float g_ns[NMAX];
__device__ float g_nd[NMAX];

// ---------------- init ----------------
__global__ void zero_deg_kernel(int N) {
    int t = blockIdx.x * blockDim.x + threadIdx.x;
    if (t < N) { g_din[t] = 0; g_dout[t] = 0; }
}

__global__ void degree_kernel(const int* __restrict__ src, const int* __restrict__ dst, int E) {
    int e = blockIdx.x * blockDim.x + threadIdx.x;
    if (e >= E) return;
    atomicAdd(&g_dout[src[e]], 1);
    atomicAdd(&g_din [dst[e]], 1);
}

__global__ void norm_kernel(int N) {
    int t = blockIdx.x * blockDim.x + threadIdx.x;
    if (t >= N) return;
    g_ns[t] = rsqrtf(fmaxf((float)g_dout[t], 1.f));
    g_nd[t] = rsqrtf(fmaxf((float)g_din [t], 1.f));
}

// ---------------- CSR build: scan + fill ----------------
__global__ void __launch_bounds__(SCAN_T) scan_kernel(int N) {
    __shared__ int wsum[SCAN_T / 32];
    int tid   = threadIdx.x;
    int chunk = (N + SCAN_T - 1) / SCAN_T;
    int lo = tid * chunk;
    int hi = lo + chunk; if (hi > N) hi = N;
    if (lo > N) lo = N;

    int s = 0;
    for (int i = lo; i < hi; i++) s += g_din[i];

    int lane = tid & 31, wid = tid >> 5;
    int v = s;
    #pragma unroll
    for (int o = 1; o < 32; o <<= 1) {
        int t = __shfl_up_sync(0xffffffffu, v, o);
        if (lane >= o) v += t;
    }
    if (lane == 31) wsum[wid] = v;
    __syncthreads();
    if (wid == 0) {
        int wv = wsum[lane];
        #pragma unroll
        for (int o = 1; o < 32; o <<= 1) {
            int t = __shfl_up_sync(0xffffffffu, wv, o);
            if (lane >= o) wv += t;
        }
        wsum[lane] = wv;
    }
    __syncthreads();

    int excl = v - s + (wid > 0 ? wsum[wid - 1] : 0);
    int run = excl;
    for (int i = lo; i < hi; i++) {
        g_rowptr[i] = run;
        g_cursor[i] = run;
        run += g_din[i];
    }
    if (tid == SCAN_T - 1) g_rowptr[N] = run;
}

__global__ void fill_kernel(const int* __restrict__ src, const int* __restrict__ dst, int E) {
    int e = blockIdx.x * blockDim.x + threadIdx.x;
    if (e >= E) return;
    int pos = atomicAdd(&g_cursor[dst[e]], 1);
    g_csrsrc[pos] = src[e];
}

// ---------------- GEMM: g_x[N,128] = (A .* ns) @ W[128,128] ----------------
// 128x128x16 tiles, 256 threads, 8x8 microtile. a_sel: 0 -> A_ext, 1 -> g_h.
#define BM 128
#define BK 16

__global__ void __launch_bounds__(256) gemm_kernel(
    const float* __restrict__ A_ext, const float* __restrict__ W, int N, int a_sel)
{
    const float* A = a_sel ? (const float*)g_h : A_ext;

    __shared__ float As[BK][BM + 4];   // transposed [k][m], stride 132
    __shared__ float Ws[BK][FDIM];

    const int m0  = blockIdx.x * BM;
    const int tid = threadIdx.x;
    const int tx  = tid & 15;          // col group
    const int ty  = tid >> 4;          // row group

    float acc[8][8];
    #pragma unroll
    for (int i = 0; i < 8; i++)
        #pragma unroll
        for (int j = 0; j < 8; j++) acc[i][j] = 0.f;

    #pragma unroll
    for (int k0 = 0; k0 < FDIM; k0 += BK) {
        // A tile 128x16 (512 float4, 2/thread), row-scaled, stored transposed
        #pragma unroll
        for (int i = 0; i < 2; i++) {
            int lin = tid + i * 256;
            int r   = lin >> 2;            // 0..127
            int c   = (lin & 3) << 2;      // 0,4,8,12
            int row = m0 + r;
            float4 v = make_float4(0.f, 0.f, 0.f, 0.f);
            float  s = 0.f;
            if (row < N) {
                v = *reinterpret_cast<const float4*>(A + (size_t)row * FDIM + k0 + c);
                s = g_ns[row];
            }
            As[c + 0][r] = v.x * s;
            As[c + 1][r] = v.y * s;
            As[c + 2][r] = v.z * s;
            As[c + 3][r] = v.w * s;
        }
        // W tile 16x128 (512 float4, 2/thread)
        #pragma unroll
        for (int i = 0; i < 2; i++) {
            int lin = tid + i * 256;
            int r   = lin >> 5;            // 0..15
            int c   = (lin & 31) << 2;
            *reinterpret_cast<float4*>(&Ws[r][c]) =
                *reinterpret_cast<const float4*>(W + (size_t)(k0 + r) * FDIM + c);
        }
        __syncthreads();

        #pragma unroll
        for (int kk = 0; kk < BK; kk++) {
            float a[8], w[8];
            *reinterpret_cast<float4*>(a)     = *reinterpret_cast<const float4*>(&As[kk][ty * 8]);
            *reinterpret_cast<float4*>(a + 4) = *reinterpret_cast<const float4*>(&As[kk][ty * 8 + 4]);
            *reinterpret_cast<float4*>(w)     = *reinterpret_cast<const float4*>(&Ws[kk][tx * 4]);
            *reinterpret_cast<float4*>(w + 4) = *reinterpret_cast<const float4*>(&Ws[kk][tx * 4 + 64]);
            #pragma unroll
            for (int i = 0; i < 8; i++)
                #pragma unroll
                for (int j = 0; j < 8; j++)
                    acc[i][j] = fmaf(a[i], w[j], acc[i][j]);
        }
        __syncthreads();
    }

    // store: rows m0+ty*8+i, cols tx*4..+3 and 64+tx*4..+3
    #pragma unroll
    for (int i = 0; i < 8; i++) {
        int row = m0 + ty * 8 + i;
        if (row >= N) continue;
        float* cp = g_x + (size_t)row * FDIM + tx * 4;
        *reinterpret_cast<float4*>(cp)      = make_float4(acc[i][0], acc[i][1], acc[i][2], acc[i][3]);
        *reinterpret_cast<float4*>(cp + 64) = make_float4(acc[i][4], acc[i][5], acc[i][6], acc[i][7]);
    }
}

// ---------------- SpMM-CSR: out[d] = f(sum_{e: dst=d} x[src_e]) ----------------
// warp per dst row; lane covers 4 feature cols (float4). Epilogue fused.
// o_sel: 0 -> OUT_ext, 1 -> g_h.
__global__ void __launch_bounds__(256) spmm_csr_kernel(
    const float* __restrict__ b, float* __restrict__ OUT_ext,
    int N, int do_relu, int o_sel)
{
    float* OUT = o_sel ? (float*)g_h : OUT_ext;
    int w    = (blockIdx.x * blockDim.x + threadIdx.x) >> 5;
    int lane = threadIdx.x & 31;
    if (w >= N) return;

    int beg = g_rowptr[w];
    int end = g_rowptr[w + 1];

    const float4* Xv = reinterpret_cast<const float4*>(g_x);
    float4 acc = make_float4(0.f, 0.f, 0.f, 0.f);

    for (int i = beg; i < end; i += 32) {
        int myidx = (i + lane < end) ? __ldg(&g_csrsrc[i + lane]) : 0;
        int cnt   = end - i; if (cnt > 32) cnt = 32;
        for (int jj = 0; jj < cnt; jj++) {
            int s = __shfl_sync(0xffffffffu, myidx, jj);
            float4 v = Xv[(size_t)s * 32 + lane];
            acc.x += v.x; acc.y += v.y; acc.z += v.z; acc.w += v.w;
        }
    }

    float4 bb = reinterpret_cast<const float4*>(b)[lane];
    float  nd = g_nd[w];
    acc.x = fmaf(acc.x, nd, bb.x);
    acc.y = fmaf(acc.y, nd, bb.y);
    acc.z = fmaf(acc.z, nd, bb.z);
    acc.w = fmaf(acc.w, nd, bb.w);
    if (do_relu) {
        acc.x = fmaxf(acc.x, 0.f); acc.y = fmaxf(acc.y, 0.f);
        acc.z = fmaxf(acc.z, 0.f); acc.w = fmaxf(acc.w, 0.f);
    }
    reinterpret_cast<float4*>(OUT)[(size_t)w * 32 + lane] = acc;
}

// ---------------------------------------------------------------------------
extern "C" void kernel_launch(void* const* d_in, const int* in_sizes, int n_in,
                              void* d_out, int out_size)
{
    const float* feature = (const float*)d_in[0];
    const int*   src     = (const int*)  d_in[1];
    const int*   dst     = (const int*)  d_in[2];
    const float* W1      = (const float*)d_in[3];
    const float* b1      = (const float*)d_in[4];
    const float* W2      = (const float*)d_in[5];
    const float* b2      = (const float*)d_in[6];
    float* out = (float*)d_out;

    const int N = in_sizes[0] / FDIM;
    const int E = in_sizes[1];

    const int TB = 256;
    const int grid_N    = (N + TB - 1) / TB;
    const int grid_E    = (E + TB - 1) / TB;
    const int grid_gemm = (N + BM - 1) / BM;
    const int grid_spmm = (N * 32 + TB - 1) / TB;   // warp per row

    // degrees, norms, CSR
    zero_deg_kernel<<<grid_N, TB>>>(N);
    degree_kernel  <<<grid_E, TB>>>(src, dst, E);
    norm_kernel    <<<grid_N, TB>>>(N);
    scan_kernel    <<<1, SCAN_T>>>(N);
    fill_kernel    <<<grid_E, TB>>>(src, dst, E);

    // layer 1: x1 = (feature .* ns) @ W1 -> g_x ; h1 = relu(agg .* nd + b1) -> g_h
    gemm_kernel    <<<grid_gemm, TB>>>(feature, W1, N, /*a_sel=*/0);
    spmm_csr_kernel<<<grid_spmm, TB>>>(b1, nullptr, N, /*relu=*/1, /*o_sel=*/1);

    // layer 2: x2 = (h1 .* ns) @ W2 -> g_x ; out = agg .* nd + b2 -> d_out
    gemm_kernel    <<<grid_gemm, TB>>>(nullptr, W2, N, /*a_sel=*/1);
    spmm_csr_kernel<<<grid_spmm, TB>>>(b2, out, N, /*relu=*/0, /*o_sel=*/0);
}